// round 5
// baseline (speedup 1.0000x reference)
#include <cuda_runtime.h>
#include <math.h>
#include <stdint.h>

#define NMAX  50000
#define EMAX  800000
#define NGR   128

typedef unsigned long long u2;   // packed f32x2 (lo = edge a, hi = edge b)

// ---------------- scratch (static device arrays: no allocations) ----------------
__device__ float g_raw[(size_t)NMAX * 128];   // pre-activation node features (N,4,32)
__device__ float g_act[(size_t)NMAX * 128];   // post-activation node features (N,4,32)
__device__ float g_h3 [(size_t)NMAX * 32];    // layer-3 scalar output (N,32)
__device__ float g_pool[NGR * 32];            // graph pooled (128,32)

// duplicated-packed weight tables (each u64 = {w,w})
__device__ u2 g_W1p[10 * 64];
__device__ u2 g_W2p[10 * 192];
__device__ u2 g_W3p[10 * 64];
__device__ u2 g_b1p[64];
__device__ u2 g_b2p[192];
__device__ u2 g_b3p[64];

// ---------------- f32x2 helpers ----------------
__device__ __forceinline__ u2 pk2(float lo, float hi) {
    u2 r; asm("mov.b64 %0, {%1,%2};" : "=l"(r) : "f"(lo), "f"(hi)); return r;
}
__device__ __forceinline__ void upk(float& lo, float& hi, u2 v) {
    asm("mov.b64 {%0,%1}, %2;" : "=f"(lo), "=f"(hi) : "l"(v));
}
__device__ __forceinline__ u2 fma2(u2 a, u2 b, u2 c) {
    u2 d; asm("fma.rn.f32x2 %0, %1, %2, %3;" : "=l"(d) : "l"(a), "l"(b), "l"(c)); return d;
}
__device__ __forceinline__ u2 mul2(u2 a, u2 b) {
    u2 d; asm("mul.rn.f32x2 %0, %1, %2;" : "=l"(d) : "l"(a), "l"(b)); return d;
}
__device__ __forceinline__ u2 neg2(u2 a) { return a ^ 0x8000000080000000ULL; }
__device__ __forceinline__ u2 dupf(float v) {
    u2 b = (u2)__float_as_uint(v); return b | (b << 32);   // constant-folds for literals
}

// ---------------- scalar helpers ----------------
__device__ __forceinline__ float sspf(float x) {
    return fmaxf(x, 0.f) + log1pf(__expf(-fabsf(x))) - 0.69314718055994530942f;
}
__device__ __forceinline__ void red_add(float* p, float v) {
    asm volatile("red.global.add.f32 [%0], %1;" :: "l"(p), "f"(v) : "memory");
}
__device__ __forceinline__ float cutoff_w(float d) {
    float u = d * (1.0f / 1.5f);
    if (u >= 1.f) return 0.f;
    float u2v = u * u;
    float u6 = u2v * u2v * u2v;
    return 1.f + u6 * (-28.f + u * (48.f - 21.f * u));
}
__device__ __forceinline__ float emb_lane(float d, int lane) {
    if (lane >= 10) return 0.f;
    float mu = 0.7f + (float)lane * 0.111111111111111111f;
    float t = d - mu;
    return __expf(-50.f * t * t);
}

// ---------------- prep: duplicate-pack W/b tables ----------------
__global__ void k_prep(const float* __restrict__ W1, const float* __restrict__ b1,
                       const float* __restrict__ W2, const float* __restrict__ b2,
                       const float* __restrict__ W3, const float* __restrict__ b3)
{
    int t = blockIdx.x * blockDim.x + threadIdx.x;
    if (t < 640)  g_W1p[t] = dupf(W1[t]);
    if (t < 1920) g_W2p[t] = dupf(W2[t]);
    if (t < 640)  g_W3p[t] = dupf(W3[t]);
    if (t < 64)   g_b1p[t] = dupf(b1[t]);
    if (t < 192)  g_b2p[t] = dupf(b2[t]);
    if (t < 64)   g_b3p[t] = dupf(b3[t]);
}

// ---------------- common per-warp edge prologue ----------------
#define EDGE_PROLOGUE                                                          \
    int warp = (blockIdx.x * blockDim.x + threadIdx.x) >> 5;                   \
    int lane = threadIdx.x & 31;                                               \
    int e0 = warp * 4;                                                         \
    if (e0 >= E) return;                                                       \
    int src[4], dst[4];                                                        \
    float ew[4], embv[4];                                                      \
    _Pragma("unroll")                                                          \
    for (int e = 0; e < 4; e++) {                                              \
        int idx = e0 + e;                                                      \
        bool v = idx < E;                                                      \
        int id2 = v ? idx : 0;                                                 \
        src[e] = ei[id2];                                                      \
        dst[e] = ei[E + id2];                                                  \
        float d = elen[id2];                                                   \
        ew[e] = v ? cutoff_w(d) : 0.f;                                         \
        embv[e] = emb_lane(d, lane);                                           \
    }

// ---------------- layer 1 ----------------
__global__ void __launch_bounds__(256) k_layer1(
    const float* __restrict__ x, const float* __restrict__ esh,
    const float* __restrict__ elen, const int* __restrict__ ei, int E)
{
    EDGE_PROLOGUE

    u2 wa[2], wb[2];
    { u2 b0 = g_b1p[lane], bv = g_b1p[32 + lane]; wa[0] = wa[1] = b0; wb[0] = wb[1] = bv; }
    #pragma unroll
    for (int k = 0; k < 10; k++) {
        u2 w0 = g_W1p[k * 64 + lane];
        u2 w1 = g_W1p[k * 64 + 32 + lane];
        #pragma unroll
        for (int pr = 0; pr < 2; pr++) {
            float ea = __shfl_sync(0xffffffffu, embv[2 * pr], k);
            float eb = __shfl_sync(0xffffffffu, embv[2 * pr + 1], k);
            u2 ekp = pk2(ea, eb);
            wa[pr] = fma2(ekp, w0, wa[pr]);
            wb[pr] = fma2(ekp, w1, wb[pr]);
        }
    }

    #pragma unroll
    for (int pr = 0; pr < 2; pr++) {
        int ia = e0 + 2 * pr;     if (ia >= E) ia = E - 1;
        int ib = e0 + 2 * pr + 1; if (ib >= E) ib = E - 1;
        const float* sa = esh + (size_t)ia * 9;
        const float* sb = esh + (size_t)ib * 9;
        u2 s0  = pk2(sa[0], sb[0]);
        u2 sv0 = pk2(sa[1], sb[1]);
        u2 sv1 = pk2(sa[2], sb[2]);
        u2 sv2 = pk2(sa[3], sb[3]);
        u2 xs  = pk2(x[src[2 * pr]] * ew[2 * pr], x[src[2 * pr + 1]] * ew[2 * pr + 1]);

        u2 ms = mul2(mul2(xs, s0), wa[pr]);
        u2 xw = mul2(xs, wb[pr]);
        u2 m1 = mul2(xw, sv0);
        u2 m2 = mul2(xw, sv1);
        u2 m3 = mul2(xw, sv2);

        float lo, hi;
        float* pa = g_raw + (size_t)dst[2 * pr] * 128 + lane;
        float* pb = g_raw + (size_t)dst[2 * pr + 1] * 128 + lane;
        upk(lo, hi, ms); red_add(pa,      lo); red_add(pb,      hi);
        upk(lo, hi, m1); red_add(pa + 32, lo); red_add(pb + 32, hi);
        upk(lo, hi, m2); red_add(pa + 64, lo); red_add(pb + 64, hi);
        upk(lo, hi, m3); red_add(pa + 96, lo); red_add(pb + 96, hi);
    }
}

// ---------------- norm-act ----------------
__global__ void k_normact(int N, int zero_raw)
{
    int t = blockIdx.x * blockDim.x + threadIdx.x;
    if (t >= N * 32) return;
    int n = t >> 5, c = t & 31;
    float* ip = g_raw + (size_t)n * 128;
    float s  = ip[c];
    float v0 = ip[32 + c], v1 = ip[64 + c], v2 = ip[96 + c];
    float nr = sqrtf(v0 * v0 + v1 * v1 + v2 * v2 + 1e-12f);
    float sc = sspf(nr) / nr;
    float* op = g_act + (size_t)n * 128;
    op[c]      = sspf(s);
    op[32 + c] = v0 * sc;
    op[64 + c] = v1 * sc;
    op[96 + c] = v2 * sc;
    if (zero_raw) {
        ip[c] = 0.f; ip[32 + c] = 0.f; ip[64 + c] = 0.f; ip[96 + c] = 0.f;
    }
}

// ---------------- layer 2 ----------------
__global__ void __launch_bounds__(256) k_layer2(
    const float* __restrict__ esh, const float* __restrict__ elen,
    const int* __restrict__ ei, int E)
{
    EDGE_PROLOGUE

    u2 wp[2][6];
    #pragma unroll
    for (int p = 0; p < 6; p++) {
        u2 bv = g_b2p[p * 32 + lane];
        wp[0][p] = bv; wp[1][p] = bv;
    }
    #pragma unroll
    for (int k = 0; k < 10; k++) {
        u2 w[6];
        #pragma unroll
        for (int p = 0; p < 6; p++) w[p] = g_W2p[k * 192 + p * 32 + lane];
        #pragma unroll
        for (int pr = 0; pr < 2; pr++) {
            float ea = __shfl_sync(0xffffffffu, embv[2 * pr], k);
            float eb = __shfl_sync(0xffffffffu, embv[2 * pr + 1], k);
            u2 ekp = pk2(ea, eb);
            #pragma unroll
            for (int p = 0; p < 6; p++) wp[pr][p] = fma2(ekp, w[p], wp[pr][p]);
        }
    }

    const u2 C_nRT3 = dupf(-0.57735026918962576451f);  // -1/sqrt(3)
    const u2 C_nRT2 = dupf(-0.70710678118654752440f);  // -1/sqrt(2)
    const u2 C_A    = dupf( 0.31622776601683793320f);  // 1/sqrt(10)
    const u2 C_2A   = dupf( 0.63245553203367586640f);  // 2/sqrt(10)
    const u2 C_B    = dupf( 0.54772255750516611346f);  // sqrt(3/10)

    #pragma unroll
    for (int pr = 0; pr < 2; pr++) {
        int ia = e0 + 2 * pr;     if (ia >= E) ia = E - 1;
        int ib = e0 + 2 * pr + 1; if (ib >= E) ib = E - 1;
        const float* sa = esh + (size_t)ia * 9;
        const float* sb = esh + (size_t)ib * 9;
        u2 s0  = pk2(sa[0], sb[0]);
        u2 sv0 = pk2(sa[1], sb[1]);
        u2 sv1 = pk2(sa[2], sb[2]);
        u2 sv2 = pk2(sa[3], sb[3]);
        u2 t20 = pk2(sa[4], sb[4]);
        u2 t21 = pk2(sa[5], sb[5]);
        u2 t22 = pk2(sa[6], sb[6]);
        u2 t23 = pk2(sa[7], sb[7]);
        u2 t24 = pk2(sa[8], sb[8]);

        const float* xa = g_act + (size_t)src[2 * pr] * 128 + lane;
        const float* xb = g_act + (size_t)src[2 * pr + 1] * 128 + lane;
        u2 x0  = pk2(xa[0],  xb[0]);
        u2 xv0 = pk2(xa[32], xb[32]);
        u2 xv1 = pk2(xa[64], xb[64]);
        u2 xv2 = pk2(xa[96], xb[96]);

        u2 nxv0 = neg2(xv0), nxv1 = neg2(xv1), nxv2 = neg2(xv2);

        // paths (0,0,0) + (1,1,0)
        u2 dotv = fma2(xv2, sv2, fma2(xv1, sv1, mul2(xv0, sv0)));
        u2 m0 = fma2(mul2(dotv, C_nRT3), wp[pr][3], mul2(mul2(s0, x0), wp[pr][0]));

        // path (1,1,1): cross
        u2 cr0 = fma2(nxv2, sv1, mul2(xv1, sv2));
        u2 cr1 = fma2(nxv0, sv2, mul2(xv2, sv0));
        u2 cr2 = fma2(nxv1, sv0, mul2(xv0, sv1));

        // path (1,2,1)
        u2 axv0   = mul2(xv0, C_A);
        u2 bxv0   = mul2(xv0, C_B);
        u2 nbxv0  = neg2(bxv0);
        u2 nbxv1  = mul2(nxv1, C_B);
        u2 nbxv2  = mul2(nxv2, C_B);
        u2 n2axv1 = mul2(nxv1, C_2A);
        u2 axv2   = mul2(xv2, C_A);
        u2 t50 = fma2(nbxv2, t20, fma2(nbxv1, t21, fma2(bxv0, t24, mul2(axv0, t22))));
        u2 t51 = fma2(nbxv2, t23, fma2(n2axv1, t22, mul2(nbxv0, t21)));
        u2 t52 = fma2(nbxv2, t24, fma2(axv2, t22, fma2(nbxv1, t23, mul2(nbxv0, t20))));

        u2 x0w1 = mul2(x0, wp[pr][1]);
        u2 s0w2 = mul2(s0, wp[pr][2]);
        u2 wn4  = mul2(wp[pr][4], C_nRT2);
        u2 m1 = fma2(t50, wp[pr][5], fma2(cr0, wn4, fma2(xv0, s0w2, mul2(sv0, x0w1))));
        u2 m2 = fma2(t51, wp[pr][5], fma2(cr1, wn4, fma2(xv1, s0w2, mul2(sv1, x0w1))));
        u2 m3 = fma2(t52, wp[pr][5], fma2(cr2, wn4, fma2(xv2, s0w2, mul2(sv2, x0w1))));

        u2 ewp = pk2(ew[2 * pr], ew[2 * pr + 1]);
        m0 = mul2(m0, ewp);
        m1 = mul2(m1, ewp);
        m2 = mul2(m2, ewp);
        m3 = mul2(m3, ewp);

        float lo, hi;
        float* pa = g_raw + (size_t)dst[2 * pr] * 128 + lane;
        float* pb = g_raw + (size_t)dst[2 * pr + 1] * 128 + lane;
        upk(lo, hi, m0); red_add(pa,      lo); red_add(pb,      hi);
        upk(lo, hi, m1); red_add(pa + 32, lo); red_add(pb + 32, hi);
        upk(lo, hi, m2); red_add(pa + 64, lo); red_add(pb + 64, hi);
        upk(lo, hi, m3); red_add(pa + 96, lo); red_add(pb + 96, hi);
    }
}

// ---------------- layer 3 ----------------
__global__ void __launch_bounds__(256) k_layer3(
    const float* __restrict__ esh, const float* __restrict__ elen,
    const int* __restrict__ ei, int E)
{
    EDGE_PROLOGUE

    u2 wa[2], wb[2];
    { u2 b0 = g_b3p[lane], bv = g_b3p[32 + lane]; wa[0] = wa[1] = b0; wb[0] = wb[1] = bv; }
    #pragma unroll
    for (int k = 0; k < 10; k++) {
        u2 w0 = g_W3p[k * 64 + lane];
        u2 w1 = g_W3p[k * 64 + 32 + lane];
        #pragma unroll
        for (int pr = 0; pr < 2; pr++) {
            float ea = __shfl_sync(0xffffffffu, embv[2 * pr], k);
            float eb = __shfl_sync(0xffffffffu, embv[2 * pr + 1], k);
            u2 ekp = pk2(ea, eb);
            wa[pr] = fma2(ekp, w0, wa[pr]);
            wb[pr] = fma2(ekp, w1, wb[pr]);
        }
    }

    const u2 C_nRT3 = dupf(-0.57735026918962576451f);
    #pragma unroll
    for (int pr = 0; pr < 2; pr++) {
        int ia = e0 + 2 * pr;     if (ia >= E) ia = E - 1;
        int ib = e0 + 2 * pr + 1; if (ib >= E) ib = E - 1;
        const float* sa = esh + (size_t)ia * 9;
        const float* sb = esh + (size_t)ib * 9;
        u2 s0  = pk2(sa[0], sb[0]);
        u2 sv0 = pk2(sa[1], sb[1]);
        u2 sv1 = pk2(sa[2], sb[2]);
        u2 sv2 = pk2(sa[3], sb[3]);

        const float* xa = g_act + (size_t)src[2 * pr] * 128 + lane;
        const float* xb = g_act + (size_t)src[2 * pr + 1] * 128 + lane;
        u2 x0  = pk2(xa[0],  xb[0]);
        u2 xv0 = pk2(xa[32], xb[32]);
        u2 xv1 = pk2(xa[64], xb[64]);
        u2 xv2 = pk2(xa[96], xb[96]);

        u2 dotv = fma2(xv2, sv2, fma2(xv1, sv1, mul2(xv0, sv0)));
        u2 t = mul2(mul2(x0, s0), wa[pr]);
        u2 m = mul2(fma2(mul2(dotv, C_nRT3), wb[pr], t), pk2(ew[2 * pr], ew[2 * pr + 1]));

        float lo, hi;
        upk(lo, hi, m);
        red_add(g_h3 + (size_t)dst[2 * pr] * 32 + lane,     lo);
        red_add(g_h3 + (size_t)dst[2 * pr + 1] * 32 + lane, hi);
    }
}

// ---------------- silu + graph pooling ----------------
__global__ void k_pool(const int* __restrict__ batch, int N)
{
    int t = blockIdx.x * blockDim.x + threadIdx.x;
    if (t >= N * 32) return;
    int n = t >> 5, c = t & 31;
    float h = g_h3[(size_t)n * 32 + c];
    float y = h / (1.f + __expf(-h));
    atomicAdd(&g_pool[__ldg(&batch[n]) * 32 + c], y);
}

// ---------------- head ----------------
__global__ void k_head(const float* __restrict__ Wo, const float* __restrict__ bo,
                       float* __restrict__ out)
{
    __shared__ float Ws[32 * 8];
    __shared__ float bs[8];
    int t = threadIdx.x;
    if (t < 256) Ws[t] = Wo[t];
    if (t < 8)   bs[t] = bo[t];
    __syncthreads();
    if (t < NGR) {
        float acc[8];
        #pragma unroll
        for (int j = 0; j < 8; j++) acc[j] = bs[j];
        #pragma unroll
        for (int k = 0; k < 32; k++) {
            float gv = g_pool[t * 32 + k];
            #pragma unroll
            for (int j = 0; j < 8; j++) acc[j] = fmaf(gv, Ws[k * 8 + j], acc[j]);
        }
        float mx = acc[0];
        #pragma unroll
        for (int j = 1; j < 8; j++) mx = fmaxf(mx, acc[j]);
        float sm = 0.f;
        #pragma unroll
        for (int j = 0; j < 8; j++) { acc[j] = __expf(acc[j] - mx); sm += acc[j]; }
        float inv = 1.f / sm;
        #pragma unroll
        for (int j = 0; j < 8; j++) out[t * 8 + j] = acc[j] * inv;
    }
}

// ---------------- host ----------------
extern "C" void kernel_launch(void* const* d_in, const int* in_sizes, int n_in,
                              void* d_out, int out_size)
{
    int ix, ish, ilen, iW1, ib1, iW2, ib2, iW3, ib3, iWo, ibo, iei, ibatch;
    if (n_in >= 13 && (long long)in_sizes[1] == 9LL * (long long)in_sizes[2]) {
        ix = 0; ish = 1; ilen = 2; iW1 = 3; ib1 = 4; iW2 = 5; ib2 = 6;
        iW3 = 7; ib3 = 8; iWo = 9; ibo = 10; iei = 11; ibatch = 12;
    } else {
        ix = 0; iei = 1; ish = 2; ilen = 3; ibatch = 4; iW1 = 5; ib1 = 6;
        iW2 = 7; ib2 = 8; iW3 = 9; ib3 = 10; iWo = 11; ibo = 12;
    }

    const float* x     = (const float*)d_in[ix];
    const float* esh   = (const float*)d_in[ish];
    const float* elen  = (const float*)d_in[ilen];
    const float* W1    = (const float*)d_in[iW1];
    const float* b1    = (const float*)d_in[ib1];
    const float* W2    = (const float*)d_in[iW2];
    const float* b2    = (const float*)d_in[ib2];
    const float* W3    = (const float*)d_in[iW3];
    const float* b3    = (const float*)d_in[ib3];
    const float* Wo    = (const float*)d_in[iWo];
    const float* bo    = (const float*)d_in[ibo];
    const int*   ei    = (const int*)d_in[iei];
    const int*   batch = (const int*)d_in[ibatch];

    int N = in_sizes[ix];
    int E = in_sizes[ilen];
    if (N > NMAX) N = NMAX;
    if (E > EMAX) E = EMAX;

    void *praw, *ph3, *ppool;
    cudaGetSymbolAddress(&praw, g_raw);
    cudaGetSymbolAddress(&ph3, g_h3);
    cudaGetSymbolAddress(&ppool, g_pool);

    int nwarps = (E + 3) / 4;
    int nbE = (nwarps * 32 + 255) / 256;
    int nbN = (N * 32 + 255) / 256;

    // prep packed tables + zero scratch
    k_prep<<<8, 256>>>(W1, b1, W2, b2, W3, b3);
    cudaMemsetAsync(praw, 0, (size_t)N * 128 * sizeof(float), 0);

    // Layer 1
    k_layer1<<<nbE, 256>>>(x, esh, elen, ei, E);
    k_normact<<<nbN, 256>>>(N, /*zero_raw=*/1);

    // Layer 2
    k_layer2<<<nbE, 256>>>(esh, elen, ei, E);
    k_normact<<<nbN, 256>>>(N, /*zero_raw=*/0);

    // Layer 3 + pooling + head
    cudaMemsetAsync(ph3, 0, (size_t)N * 32 * sizeof(float), 0);
    cudaMemsetAsync(ppool, 0, (size_t)NGR * 32 * sizeof(float), 0);
    k_layer3<<<nbE, 256>>>(esh, elen, ei, E);
    k_pool<<<nbN, 256>>>(batch, N);
    k_head<<<1, 256>>>(Wo, bo, (float*)d_out);
}